// round 7
// baseline (speedup 1.0000x reference)
#include <cuda_runtime.h>
#include <cuda_bf16.h>
#include <cstdint>

// Problem constants: C=64 in-channels, T=8 terms, F=64 out.
#define C_DIM 64
#define T_DIM 8
#define F_DIM 64
#define TC_DIM 512  // T*C

#define EMAX 800000
#define NOUTMAX 50176  // 50000 rounded up to multiple of 128

typedef unsigned long long ull;
typedef unsigned int uint;

// ---------------- scratch (__device__ globals; no allocations allowed) ----------
__device__ int   g_is64;
__device__ int   g_count[NOUTMAX];
__device__ ull   g_state[64];                 // decoupled-lookback scan state
__device__ int   g_offsets[NOUTMAX + 1];
__device__ uint  g_rank[EMAX];                // (o << 12) | rank-within-bin
__device__ int   g_src[EMAX];                 // idx_in per CSR slot
__device__ float g_edgeW[(size_t)EMAX * T_DIM];
// Packed bf16 hi/lo planes: low16 = hi(bf16 of v), high16 = lo(bf16 of v-hi).
// K-dim permuted for mma fragment loads. Zero-init pad rows = +0.0bf16, safe.
__device__ uint g_Mp[(size_t)NOUTMAX * TC_DIM];
__device__ uint g_Kp[F_DIM * TC_DIM];         // [n][k'] = pack(Kf[k][n])

// K-dim permutation: within each 16-element group, reorder so lane (t=k-pair idx)
// finds its 4 fragment elements {2t,2t+1,2t+8,2t+9} contiguous at offset t*4.
// Note: preserves bit0, so channel pairs (2j, 2j+1) stay adjacent.
__device__ __forceinline__ int permk(int k) {
    return (k & ~15) | (((k >> 1) & 3) << 2) | (((k >> 3) & 1) << 1) | (k & 1);
}

// ---------------- index dtype helper --------------------------------------------
__device__ __forceinline__ int idx_at(const void* p, long long i) {
    if (g_is64) return (int)((const long long*)p)[i];
    return ((const int*)p)[i];
}

__device__ __forceinline__ uint split_pack(float v) {
    __nv_bfloat16 h = __float2bfloat16(v);
    float hf = __bfloat162float(h);
    __nv_bfloat16 l = __float2bfloat16(v - hf);
    return (uint)__bfloat16_as_ushort(h) | ((uint)__bfloat16_as_ushort(l) << 16);
}

// ---------------- init: zero counters/state + prep K + detect index dtype --------
__global__ void k_init(int nOut, const void* idx, const float* __restrict__ Kf) {
    int i = blockIdx.x * blockDim.x + threadIdx.x;
    if (i < nOut) g_count[i] = 0;
    if (i < 64) g_state[i] = 0ull;
    if (i < TC_DIM * F_DIM) {
        int k = i >> 6, n = i & 63;
        g_Kp[(size_t)n * TC_DIM + permk(k)] = split_pack(Kf[i]);
    }
    if (i == 0) {
        // int64 (nonneg < 2^31): every odd 32-bit word is zero.
        const unsigned* w = (const unsigned*)idx;
        int is64 = 1;
        for (int j = 0; j < 64; j++) {
            if (w[2 * j + 1] != 0u) { is64 = 0; break; }
        }
        g_is64 = is64;
    }
}

// Histogram; store (o << 12) | rank so fill never re-reads idx_out.
// (Degrees are Poisson(E/N_OUT = 16); rank < 4096 by enormous margin.)
__global__ void k_hist(const void* idx, int E) {
    int e = blockIdx.x * blockDim.x + threadIdx.x;
    if (e < E) {
        int o = idx_at(idx, 2LL * e);
        uint r = (uint)atomicAdd(&g_count[o], 1);
        g_rank[e] = ((uint)o << 12) | r;
    }
}

// ---------------- single-pass scan with decoupled lookback -----------------------
#define FLAG_AGG (1ull << 32)
#define FLAG_PFX (2ull << 32)

__global__ void k_scan(int nOut, int E) {
    __shared__ int wsum[32];
    __shared__ int sh_total;
    __shared__ int sh_excl;
    int tid = threadIdx.x;
    int lane = tid & 31, wid = tid >> 5;
    int b = blockIdx.x;
    int i = b * 1024 + tid;
    int v = (i < nOut) ? g_count[i] : 0;

    int s = v;
#pragma unroll
    for (int off = 1; off < 32; off <<= 1) {
        int t = __shfl_up_sync(0xffffffffu, s, off);
        if (lane >= off) s += t;
    }
    if (lane == 31) wsum[wid] = s;
    __syncthreads();
    if (wid == 0) {
        int ws = wsum[lane];
#pragma unroll
        for (int off = 1; off < 32; off <<= 1) {
            int t = __shfl_up_sync(0xffffffffu, ws, off);
            if (lane >= off) ws += t;
        }
        wsum[lane] = ws;
    }
    __syncthreads();
    int incl = s + (wid > 0 ? wsum[wid - 1] : 0);
    if (tid == 1023) sh_total = incl;
    __syncthreads();

    if (tid == 0) {
        int total = sh_total;
        if (b == 0) {
            atomicExch(&g_state[0], FLAG_PFX | (unsigned)total);
            sh_excl = 0;
        } else {
            atomicExch(&g_state[b], FLAG_AGG | (unsigned)total);
            int run = 0;
            for (int j = b - 1; j >= 0;) {
                ull st;
                do { st = atomicAdd(&g_state[j], 0ull); } while ((st >> 32) == 0ull);
                run += (int)(unsigned)st;
                if ((st >> 32) == 2ull) break;
                j--;
            }
            atomicExch(&g_state[b], FLAG_PFX | (unsigned)(run + total));
            sh_excl = run;
        }
    }
    __syncthreads();

    int excl = sh_excl + incl - v;
    if (i < nOut) g_offsets[i] = excl;
    if (b == 0 && tid == 0) g_offsets[nOut] = E;
}

// Fill CSR (atomic-free): p = offsets[o] + rank, with o/rank unpacked from
// g_rank. Pre-gathers edge weights transposed to (slot, T).
__global__ void k_fill(const void* idx, const float* __restrict__ edge, int E) {
    int e = blockIdx.x * blockDim.x + threadIdx.x;
    if (e >= E) return;
    uint pr = g_rank[e];
    int o = (int)(pr >> 12);
    int in = idx_at(idx, 2LL * e + 1);
    int p = g_offsets[o] + (int)(pr & 0xFFFu);
    g_src[p] = in;
    float w[T_DIM];
#pragma unroll
    for (int t = 0; t < T_DIM; t++) w[t] = edge[(size_t)t * E + e];
    float4* dst = reinterpret_cast<float4*>(g_edgeW + (size_t)p * 8);
    dst[0] = make_float4(w[0], w[1], w[2], w[3]);
    dst[1] = make_float4(w[4], w[5], w[6], w[7]);
}

// ---------------- edge accumulation: M[o, t*64+c] --------------------------------
// One warp per output; each lane owns channels (2*lane, 2*lane+1).
// src values for a 32-edge chunk are prefetched with one coalesced load and
// broadcast via shfl, removing the serial src->node dependent-load chain.
__global__ void k_accum(const float* __restrict__ node, int nOut) {
    int warp = (blockIdx.x * blockDim.x + threadIdx.x) >> 5;
    int lane = threadIdx.x & 31;
    if (warp >= nOut) return;

    int beg = g_offsets[warp];
    int end = g_offsets[warp + 1];

    float sx[T_DIM], sy[T_DIM];
#pragma unroll
    for (int t = 0; t < T_DIM; t++) { sx[t] = 0.f; sy[t] = 0.f; }

    for (int base = beg; base < end; base += 32) {
        int rem = end - base;
        int n = rem < 32 ? rem : 32;
        int mysrc = (lane < rem) ? g_src[base + lane] : 0;
#pragma unroll 4
        for (int j = 0; j < n; j++) {
            int in = __shfl_sync(0xffffffffu, mysrc, j);
            const float4* wp = reinterpret_cast<const float4*>(g_edgeW + (size_t)(base + j) * 8);
            float4 wa = wp[0];
            float4 wb = wp[1];
            float2 nv = *reinterpret_cast<const float2*>(&node[(size_t)in * C_DIM + lane * 2]);
            sx[0] += wa.x * nv.x; sy[0] += wa.x * nv.y;
            sx[1] += wa.y * nv.x; sy[1] += wa.y * nv.y;
            sx[2] += wa.z * nv.x; sy[2] += wa.z * nv.y;
            sx[3] += wa.w * nv.x; sy[3] += wa.w * nv.y;
            sx[4] += wb.x * nv.x; sy[4] += wb.x * nv.y;
            sx[5] += wb.y * nv.x; sy[5] += wb.y * nv.y;
            sx[6] += wb.z * nv.x; sy[6] += wb.z * nv.y;
            sx[7] += wb.w * nv.x; sy[7] += wb.w * nv.y;
        }
    }

    int pc = permk(lane * 2);  // even; pair (pc, pc+1) is this lane's channel pair
    size_t base = (size_t)warp * TC_DIM + pc;
#pragma unroll
    for (int t = 0; t < T_DIM; t++) {
        *reinterpret_cast<uint2*>(&g_Mp[base + (size_t)t * 64]) =
            make_uint2(split_pack(sx[t]), split_pack(sy[t]));
    }
}

// ---------------- GEMM via warp-level mma.sync (bf16 x3 products) ----------------
__device__ __forceinline__ void mma16816(float* d, uint a0, uint a1, uint a2, uint a3,
                                         uint b0, uint b1) {
    asm volatile(
        "mma.sync.aligned.m16n8k16.row.col.f32.bf16.bf16.f32 "
        "{%0,%1,%2,%3}, {%4,%5,%6,%7}, {%8,%9}, {%0,%1,%2,%3};"
        : "+f"(d[0]), "+f"(d[1]), "+f"(d[2]), "+f"(d[3])
        : "r"(a0), "r"(a1), "r"(a2), "r"(a3), "r"(b0), "r"(b1));
}

__device__ __forceinline__ uint prmt(uint a, uint b, uint sel) {
    uint r;
    asm("prmt.b32 %0, %1, %2, %3;" : "=r"(r) : "r"(a), "r"(b), "r"(sel));
    return r;
}

__global__ __launch_bounds__(128) void k_gemm(const float* __restrict__ bias,
                                              float* __restrict__ out, int nOut) {
    int tid = threadIdx.x, w = tid >> 5, lane = tid & 31;
    int g = lane >> 2, t = lane & 3;
    int rowbase = blockIdx.x * 128 + w * 32;

    size_t abase = (size_t)(rowbase + g) * TC_DIM + t * 4;
    size_t bbase = (size_t)g * TC_DIM + t * 4;

    float d[2][8][4];
#pragma unroll
    for (int mt = 0; mt < 2; mt++)
#pragma unroll
        for (int nt = 0; nt < 8; nt++)
#pragma unroll
            for (int r = 0; r < 4; r++) d[mt][nt][r] = 0.f;

#pragma unroll 1
    for (int k0 = 0; k0 < TC_DIM; k0 += 16) {
        // A: 4 row-groups (g, g+8, g+16, g+24), one uint4 each = 4 packed k-elems.
        uint4 q0 = *reinterpret_cast<const uint4*>(g_Mp + abase + k0);
        uint4 q1 = *reinterpret_cast<const uint4*>(g_Mp + abase + 8 * TC_DIM + k0);
        uint4 q2 = *reinterpret_cast<const uint4*>(g_Mp + abase + 16 * TC_DIM + k0);
        uint4 q3 = *reinterpret_cast<const uint4*>(g_Mp + abase + 24 * TC_DIM + k0);
        // hi plane fragments (a0,a1 per row-group)
        uint h00 = prmt(q0.x, q0.y, 0x5410), h01 = prmt(q0.z, q0.w, 0x5410);
        uint h10 = prmt(q1.x, q1.y, 0x5410), h11 = prmt(q1.z, q1.w, 0x5410);
        uint h20 = prmt(q2.x, q2.y, 0x5410), h21 = prmt(q2.z, q2.w, 0x5410);
        uint h30 = prmt(q3.x, q3.y, 0x5410), h31 = prmt(q3.z, q3.w, 0x5410);
        // lo plane fragments
        uint l00 = prmt(q0.x, q0.y, 0x7632), l01 = prmt(q0.z, q0.w, 0x7632);
        uint l10 = prmt(q1.x, q1.y, 0x7632), l11 = prmt(q1.z, q1.w, 0x7632);
        uint l20 = prmt(q2.x, q2.y, 0x7632), l21 = prmt(q2.z, q2.w, 0x7632);
        uint l30 = prmt(q3.x, q3.y, 0x7632), l31 = prmt(q3.z, q3.w, 0x7632);

#pragma unroll
        for (int nt = 0; nt < 8; nt++) {
            uint4 qb = *reinterpret_cast<const uint4*>(g_Kp + bbase + (size_t)nt * 8 * TC_DIM + k0);
            uint bh0 = prmt(qb.x, qb.y, 0x5410), bh1 = prmt(qb.z, qb.w, 0x5410);
            uint bl0 = prmt(qb.x, qb.y, 0x7632), bl1 = prmt(qb.z, qb.w, 0x7632);
            // d += Mh*Kh + Mh*Kl + Ml*Kh  (all into same accumulators)
            mma16816(d[0][nt], h00, h10, h01, h11, bh0, bh1);
            mma16816(d[0][nt], h00, h10, h01, h11, bl0, bl1);
            mma16816(d[0][nt], l00, l10, l01, l11, bh0, bh1);
            mma16816(d[1][nt], h20, h30, h21, h31, bh0, bh1);
            mma16816(d[1][nt], h20, h30, h21, h31, bl0, bl1);
            mma16816(d[1][nt], l20, l30, l21, l31, bh0, bh1);
        }
    }

    // Epilogue: d0=(g,2t) d1=(g,2t+1) d2=(g+8,2t) d3=(g+8,2t+1) per 16x8 tile.
#pragma unroll
    for (int mt = 0; mt < 2; mt++) {
#pragma unroll
        for (int nt = 0; nt < 8; nt++) {
            int col = nt * 8 + t * 2;
            float2 bv = *reinterpret_cast<const float2*>(bias + col);
            int r0 = rowbase + mt * 16 + g;
            if (r0 < nOut) {
                *reinterpret_cast<float2*>(&out[(size_t)r0 * F_DIM + col]) =
                    make_float2(d[mt][nt][0] + bv.x, d[mt][nt][1] + bv.y);
            }
            int r1 = r0 + 8;
            if (r1 < nOut) {
                *reinterpret_cast<float2*>(&out[(size_t)r1 * F_DIM + col]) =
                    make_float2(d[mt][nt][2] + bv.x, d[mt][nt][3] + bv.y);
            }
        }
    }
}

// ---------------- launch ---------------------------------------------------------
extern "C" void kernel_launch(void* const* d_in, const int* in_sizes, int n_in,
                              void* d_out, int out_size) {
    const float* node = (const float*)d_in[0];
    const float* edge = (const float*)d_in[1];
    const void*  idx  = d_in[2];
    const float* kern = (const float*)d_in[3];
    const float* bias = (const float*)d_in[4];
    float* out = (float*)d_out;

    int E    = in_sizes[1] / T_DIM;   // edge_features is (T, E)
    int nOut = out_size / F_DIM;      // output is (N_OUT, F)
    int nb   = (nOut + 1023) / 1024;  // <= 64

    k_init<<<(nOut + 255) / 256, 256>>>(nOut, idx, kern);
    k_hist<<<(E + 255) / 256, 256>>>(idx, E);
    k_scan<<<nb, 1024>>>(nOut, E);
    k_fill<<<(E + 255) / 256, 256>>>(idx, edge, E);
    k_accum<<<(nOut * 32 + 255) / 256, 256>>>(node, nOut);
    k_gemm<<<(nOut + 127) / 128, 128>>>(bias, out, nOut);
}

// round 8
// speedup vs baseline: 1.2911x; 1.2911x over previous
#include <cuda_runtime.h>
#include <cuda_fp16.h>
#include <cstdint>

// Problem constants: C=64 in-channels, T=8 terms, F=64 out.
#define C_DIM 64
#define T_DIM 8
#define F_DIM 64
#define TC_DIM 512  // T*C

#define EMAX 800000
#define NOUTMAX 50176  // 50000 rounded up to multiple of 128

typedef unsigned long long ull;
typedef unsigned int uint;

// ---------------- scratch (__device__ globals; no allocations allowed) ----------
__device__ int   g_is64;
__device__ int   g_count[NOUTMAX];
__device__ ull   g_state[64];                 // decoupled-lookback scan state
__device__ int   g_offsets[NOUTMAX + 1];
__device__ uint  g_rank[EMAX];                // (o << 12) | rank-within-bin
__device__ int   g_src[EMAX];                 // idx_in per CSR slot
__device__ float g_edgeW[(size_t)EMAX * T_DIM];
// M and K^T in fp16 (single plane), K-dim permuted for mma fragment loads.
// Zero-init pad rows (never written) are +0.0h -> safe for mma.
__device__ unsigned short g_Mf[(size_t)NOUTMAX * TC_DIM];
__device__ unsigned short g_Kf[F_DIM * TC_DIM];   // [n][k'] = fp16(Kern[k][n])

// K-dim permutation: within each 16-element group, reorder so lane (t=k-pair idx)
// finds its 4 fragment elements {2t,2t+1,2t+8,2t+9} contiguous at offset t*4.
// Note: preserves bit0, so channel pairs (2j, 2j+1) stay adjacent.
__device__ __forceinline__ int permk(int k) {
    return (k & ~15) | (((k >> 1) & 3) << 2) | (((k >> 3) & 1) << 1) | (k & 1);
}

// ---------------- index dtype helper --------------------------------------------
__device__ __forceinline__ int idx_at(const void* p, long long i) {
    if (g_is64) return (int)((const long long*)p)[i];
    return ((const int*)p)[i];
}

// ---------------- init: zero counters/state + prep K + detect index dtype --------
__global__ void k_init(int nOut, const void* idx, const float* __restrict__ Kf) {
    int i = blockIdx.x * blockDim.x + threadIdx.x;
    if (i < nOut) g_count[i] = 0;
    if (i < 64) g_state[i] = 0ull;
    if (i < TC_DIM * F_DIM) {
        int k = i >> 6, n = i & 63;
        g_Kf[(size_t)n * TC_DIM + permk(k)] = __half_as_ushort(__float2half_rn(Kf[i]));
    }
    if (i == 0) {
        // int64 (nonneg < 2^31): every odd 32-bit word is zero.
        const unsigned* w = (const unsigned*)idx;
        int is64 = 1;
        for (int j = 0; j < 64; j++) {
            if (w[2 * j + 1] != 0u) { is64 = 0; break; }
        }
        g_is64 = is64;
    }
}

// Histogram; store (o << 12) | rank so fill never re-reads idx_out.
// (Degrees are Poisson(E/N_OUT = 16); rank < 4096 by enormous margin.)
__global__ void k_hist(const void* idx, int E) {
    int e = blockIdx.x * blockDim.x + threadIdx.x;
    if (e < E) {
        int o = idx_at(idx, 2LL * e);
        uint r = (uint)atomicAdd(&g_count[o], 1);
        g_rank[e] = ((uint)o << 12) | r;
    }
}

// ---------------- single-pass scan with decoupled lookback -----------------------
#define FLAG_AGG (1ull << 32)
#define FLAG_PFX (2ull << 32)

__global__ void k_scan(int nOut, int E) {
    __shared__ int wsum[32];
    __shared__ int sh_total;
    __shared__ int sh_excl;
    int tid = threadIdx.x;
    int lane = tid & 31, wid = tid >> 5;
    int b = blockIdx.x;
    int i = b * 1024 + tid;
    int v = (i < nOut) ? g_count[i] : 0;

    int s = v;
#pragma unroll
    for (int off = 1; off < 32; off <<= 1) {
        int t = __shfl_up_sync(0xffffffffu, s, off);
        if (lane >= off) s += t;
    }
    if (lane == 31) wsum[wid] = s;
    __syncthreads();
    if (wid == 0) {
        int ws = wsum[lane];
#pragma unroll
        for (int off = 1; off < 32; off <<= 1) {
            int t = __shfl_up_sync(0xffffffffu, ws, off);
            if (lane >= off) ws += t;
        }
        wsum[lane] = ws;
    }
    __syncthreads();
    int incl = s + (wid > 0 ? wsum[wid - 1] : 0);
    if (tid == 1023) sh_total = incl;
    __syncthreads();

    if (tid == 0) {
        int total = sh_total;
        if (b == 0) {
            atomicExch(&g_state[0], FLAG_PFX | (unsigned)total);
            sh_excl = 0;
        } else {
            atomicExch(&g_state[b], FLAG_AGG | (unsigned)total);
            int run = 0;
            for (int j = b - 1; j >= 0;) {
                ull st;
                do { st = atomicAdd(&g_state[j], 0ull); } while ((st >> 32) == 0ull);
                run += (int)(unsigned)st;
                if ((st >> 32) == 2ull) break;
                j--;
            }
            atomicExch(&g_state[b], FLAG_PFX | (unsigned)(run + total));
            sh_excl = run;
        }
    }
    __syncthreads();

    int excl = sh_excl + incl - v;
    if (i < nOut) g_offsets[i] = excl;
    if (b == 0 && tid == 0) g_offsets[nOut] = E;
}

// Fill CSR (atomic-free): p = offsets[o] + rank, with o/rank unpacked from
// g_rank. Pre-gathers edge weights transposed to (slot, T).
__global__ void k_fill(const void* idx, const float* __restrict__ edge, int E) {
    int e = blockIdx.x * blockDim.x + threadIdx.x;
    if (e >= E) return;
    uint pr = g_rank[e];
    int o = (int)(pr >> 12);
    int in = idx_at(idx, 2LL * e + 1);
    int p = g_offsets[o] + (int)(pr & 0xFFFu);
    g_src[p] = in;
    float w[T_DIM];
#pragma unroll
    for (int t = 0; t < T_DIM; t++) w[t] = edge[(size_t)t * E + e];
    float4* dst = reinterpret_cast<float4*>(g_edgeW + (size_t)p * 8);
    dst[0] = make_float4(w[0], w[1], w[2], w[3]);
    dst[1] = make_float4(w[4], w[5], w[6], w[7]);
}

// ---------------- edge accumulation: M[o, t*64+c] --------------------------------
// One warp per output; each lane owns channels (2*lane, 2*lane+1).  (R6 proven loop)
__global__ void k_accum(const float* __restrict__ node, int nOut) {
    int warp = (blockIdx.x * blockDim.x + threadIdx.x) >> 5;
    int lane = threadIdx.x & 31;
    if (warp >= nOut) return;

    int beg = g_offsets[warp];
    int end = g_offsets[warp + 1];

    float sx[T_DIM], sy[T_DIM];
#pragma unroll
    for (int t = 0; t < T_DIM; t++) { sx[t] = 0.f; sy[t] = 0.f; }

#pragma unroll 2
    for (int i = beg; i < end; i++) {
        int in = g_src[i];
        float4 wa = *reinterpret_cast<const float4*>(g_edgeW + (size_t)i * 8);
        float4 wb = *reinterpret_cast<const float4*>(g_edgeW + (size_t)i * 8 + 4);
        float2 nv = *reinterpret_cast<const float2*>(&node[(size_t)in * C_DIM + lane * 2]);
        sx[0] += wa.x * nv.x; sy[0] += wa.x * nv.y;
        sx[1] += wa.y * nv.x; sy[1] += wa.y * nv.y;
        sx[2] += wa.z * nv.x; sy[2] += wa.z * nv.y;
        sx[3] += wa.w * nv.x; sy[3] += wa.w * nv.y;
        sx[4] += wb.x * nv.x; sy[4] += wb.x * nv.y;
        sx[5] += wb.y * nv.x; sy[5] += wb.y * nv.y;
        sx[6] += wb.z * nv.x; sy[6] += wb.z * nv.y;
        sx[7] += wb.w * nv.x; sy[7] += wb.w * nv.y;
    }

    int pc = permk(lane * 2);  // even; pair (pc, pc+1) is this lane's channel pair
    size_t base = (size_t)warp * TC_DIM + pc;
#pragma unroll
    for (int t = 0; t < T_DIM; t++) {
        uint pk = (uint)__half_as_ushort(__float2half_rn(sx[t]))
                | ((uint)__half_as_ushort(__float2half_rn(sy[t])) << 16);
        *reinterpret_cast<uint*>(&g_Mf[base + (size_t)t * 64]) = pk;
    }
}

// ---------------- GEMM via warp-level mma.sync (single fp16 product) -------------
__device__ __forceinline__ void mma16816(float* d, uint a0, uint a1, uint a2, uint a3,
                                         uint b0, uint b1) {
    asm volatile(
        "mma.sync.aligned.m16n8k16.row.col.f32.f16.f16.f32 "
        "{%0,%1,%2,%3}, {%4,%5,%6,%7}, {%8,%9}, {%0,%1,%2,%3};"
        : "+f"(d[0]), "+f"(d[1]), "+f"(d[2]), "+f"(d[3])
        : "r"(a0), "r"(a1), "r"(a2), "r"(a3), "r"(b0), "r"(b1));
}

__global__ __launch_bounds__(128) void k_gemm(const float* __restrict__ bias,
                                              float* __restrict__ out, int nOut) {
    int tid = threadIdx.x, w = tid >> 5, lane = tid & 31;
    int g = lane >> 2, t = lane & 3;
    int rowbase = blockIdx.x * 128 + w * 32;

    size_t abase = (size_t)(rowbase + g) * TC_DIM + t * 4;
    size_t bbase = (size_t)g * TC_DIM + t * 4;

    float d[2][8][4];
#pragma unroll
    for (int mt = 0; mt < 2; mt++)
#pragma unroll
        for (int nt = 0; nt < 8; nt++)
#pragma unroll
            for (int r = 0; r < 4; r++) d[mt][nt][r] = 0.f;

#pragma unroll 2
    for (int k0 = 0; k0 < TC_DIM; k0 += 16) {
        // A: 4 row-groups (g, g+8, g+16, g+24); each LDG.64 = 4 fp16 fragment elems.
        ull A0 = *reinterpret_cast<const ull*>(g_Mf + abase + k0);
        ull A1 = *reinterpret_cast<const ull*>(g_Mf + abase + 8 * TC_DIM + k0);
        ull A2 = *reinterpret_cast<const ull*>(g_Mf + abase + 16 * TC_DIM + k0);
        ull A3 = *reinterpret_cast<const ull*>(g_Mf + abase + 24 * TC_DIM + k0);
#pragma unroll
        for (int nt = 0; nt < 8; nt++) {
            ull Bv = *reinterpret_cast<const ull*>(g_Kf + bbase + (size_t)nt * 8 * TC_DIM + k0);
            uint b0 = (uint)Bv, b1 = (uint)(Bv >> 32);
            mma16816(d[0][nt], (uint)A0, (uint)A1, (uint)(A0 >> 32), (uint)(A1 >> 32), b0, b1);
            mma16816(d[1][nt], (uint)A2, (uint)A3, (uint)(A2 >> 32), (uint)(A3 >> 32), b0, b1);
        }
    }

    // Epilogue: d0=(g,2t) d1=(g,2t+1) d2=(g+8,2t) d3=(g+8,2t+1) per 16x8 tile.
#pragma unroll
    for (int mt = 0; mt < 2; mt++) {
#pragma unroll
        for (int nt = 0; nt < 8; nt++) {
            int col = nt * 8 + t * 2;
            float2 bv = *reinterpret_cast<const float2*>(bias + col);
            int r0 = rowbase + mt * 16 + g;
            if (r0 < nOut) {
                *reinterpret_cast<float2*>(&out[(size_t)r0 * F_DIM + col]) =
                    make_float2(d[mt][nt][0] + bv.x, d[mt][nt][1] + bv.y);
            }
            int r1 = r0 + 8;
            if (r1 < nOut) {
                *reinterpret_cast<float2*>(&out[(size_t)r1 * F_DIM + col]) =
                    make_float2(d[mt][nt][2] + bv.x, d[mt][nt][3] + bv.y);
            }
        }
    }
}

// ---------------- launch ---------------------------------------------------------
extern "C" void kernel_launch(void* const* d_in, const int* in_sizes, int n_in,
                              void* d_out, int out_size) {
    const float* node = (const float*)d_in[0];
    const float* edge = (const float*)d_in[1];
    const void*  idx  = d_in[2];
    const float* kern = (const float*)d_in[3];
    const float* bias = (const float*)d_in[4];
    float* out = (float*)d_out;

    int E    = in_sizes[1] / T_DIM;   // edge_features is (T, E)
    int nOut = out_size / F_DIM;      // output is (N_OUT, F)
    int nb   = (nOut + 1023) / 1024;  // <= 64

    k_init<<<(nOut + 255) / 256, 256>>>(nOut, idx, kern);
    k_hist<<<(E + 255) / 256, 256>>>(idx, E);
    k_scan<<<nb, 1024>>>(nOut, E);
    k_fill<<<(E + 255) / 256, 256>>>(idx, edge, E);
    k_accum<<<(nOut * 32 + 255) / 256, 256>>>(node, nOut);
    k_gemm<<<(nOut + 127) / 128, 128>>>(bias, out, nOut);
}

// round 9
// speedup vs baseline: 1.4375x; 1.1134x over previous
#include <cuda_runtime.h>
#include <cuda_fp16.h>
#include <cstdint>

// Problem constants: C=64 in-channels, T=8 terms, F=64 out.
#define C_DIM 64
#define T_DIM 8
#define F_DIM 64
#define TC_DIM 512  // T*C

#define EMAX 800000
#define NOUTMAX 50176  // 50000 rounded up to multiple of 128

typedef unsigned long long ull;
typedef unsigned int uint;

// ---------------- scratch (__device__ globals; no allocations allowed) ----------
__device__ int   g_is64;
__device__ int   g_count[NOUTMAX];
__device__ ull   g_state[64];                 // decoupled-lookback scan state
__device__ int   g_offsets[NOUTMAX + 1];
__device__ uint  g_rank[EMAX];                // (o << 12) | rank-within-bin
__device__ int   g_src[EMAX];                 // idx_in per CSR slot
__device__ unsigned short g_edgeW[(size_t)EMAX * T_DIM];  // fp16, 8 per CSR slot
// M and K^T in fp16 (single plane), K-dim permuted for mma fragment loads.
// Zero-init pad rows (never written) are +0.0h -> safe for mma.
__device__ unsigned short g_Mf[(size_t)NOUTMAX * TC_DIM];
__device__ unsigned short g_Kf[F_DIM * TC_DIM];   // [n][k'] = fp16(Kern[k][n])

// K-dim permutation: within each 16-element group, reorder so lane (t=k-pair idx)
// finds its 4 fragment elements {2t,2t+1,2t+8,2t+9} contiguous at offset t*4.
// Note: preserves bit0, so channel pairs (2j, 2j+1) stay adjacent.
__device__ __forceinline__ int permk(int k) {
    return (k & ~15) | (((k >> 1) & 3) << 2) | (((k >> 3) & 1) << 1) | (k & 1);
}

// ---------------- 4-byte index readers (low word only; values < 2^31) ------------
__device__ __forceinline__ int idx_out32(const void* p, int e) {
    // element 2e: byte offset = is64 ? 16e : 8e
    const char* bp = (const char*)p;
    return *(const int*)(bp + ((size_t)e << (3 + g_is64)));
}
__device__ __forceinline__ int idx_in32(const void* p, int e) {
    // element 2e+1: byte offset = is64 ? 16e+8 : 8e+4
    const char* bp = (const char*)p;
    int sh = 3 + g_is64;
    return *(const int*)(bp + ((size_t)e << sh) + (4 << g_is64));
}

// ---------------- init: zero counters/state + prep K + detect index dtype --------
__global__ void k_init(int nOut, const void* idx, const float* __restrict__ Kf) {
    int i = blockIdx.x * blockDim.x + threadIdx.x;
    if (i == 0) {
        // int64 (nonneg < 2^31): every odd 32-bit word is zero.
        const unsigned* w = (const unsigned*)idx;
        int is64 = 1;
        for (int j = 0; j < 64; j++) {
            if (w[2 * j + 1] != 0u) { is64 = 0; break; }
        }
        g_is64 = is64;
    }
    if (i < nOut) g_count[i] = 0;
    if (i < 64) g_state[i] = 0ull;
    if (i < TC_DIM * F_DIM) {
        int k = i >> 6, n = i & 63;
        g_Kf[(size_t)n * TC_DIM + permk(k)] = __half_as_ushort(__float2half_rn(Kf[i]));
    }
}

// Histogram; store (o << 12) | rank so fill never re-reads idx_out.
// (Degrees are Poisson(E/N_OUT = 16); rank < 4096 by enormous margin.)
__global__ void k_hist(const void* idx, int E) {
    int e = blockIdx.x * blockDim.x + threadIdx.x;
    if (e < E) {
        int o = idx_out32(idx, e);
        uint r = (uint)atomicAdd(&g_count[o], 1);
        g_rank[e] = ((uint)o << 12) | r;
    }
}

// ---------------- single-pass scan with decoupled lookback -----------------------
#define FLAG_AGG (1ull << 32)
#define FLAG_PFX (2ull << 32)

__global__ void k_scan(int nOut, int E) {
    __shared__ int wsum[32];
    __shared__ int sh_total;
    __shared__ int sh_excl;
    int tid = threadIdx.x;
    int lane = tid & 31, wid = tid >> 5;
    int b = blockIdx.x;
    int i = b * 1024 + tid;
    int v = (i < nOut) ? g_count[i] : 0;

    int s = v;
#pragma unroll
    for (int off = 1; off < 32; off <<= 1) {
        int t = __shfl_up_sync(0xffffffffu, s, off);
        if (lane >= off) s += t;
    }
    if (lane == 31) wsum[wid] = s;
    __syncthreads();
    if (wid == 0) {
        int ws = wsum[lane];
#pragma unroll
        for (int off = 1; off < 32; off <<= 1) {
            int t = __shfl_up_sync(0xffffffffu, ws, off);
            if (lane >= off) ws += t;
        }
        wsum[lane] = ws;
    }
    __syncthreads();
    int incl = s + (wid > 0 ? wsum[wid - 1] : 0);
    if (tid == 1023) sh_total = incl;
    __syncthreads();

    if (tid == 0) {
        int total = sh_total;
        if (b == 0) {
            atomicExch(&g_state[0], FLAG_PFX | (unsigned)total);
            sh_excl = 0;
        } else {
            atomicExch(&g_state[b], FLAG_AGG | (unsigned)total);
            int run = 0;
            for (int j = b - 1; j >= 0;) {
                ull st;
                do { st = atomicAdd(&g_state[j], 0ull); } while ((st >> 32) == 0ull);
                run += (int)(unsigned)st;
                if ((st >> 32) == 2ull) break;
                j--;
            }
            atomicExch(&g_state[b], FLAG_PFX | (unsigned)(run + total));
            sh_excl = run;
        }
    }
    __syncthreads();

    int excl = sh_excl + incl - v;
    if (i < nOut) g_offsets[i] = excl;
    if (b == 0 && tid == 0) g_offsets[nOut] = E;
}

// Fill CSR (atomic-free): p = offsets[o] + rank, with o/rank unpacked from
// g_rank. Pre-gathers edge weights transposed to (slot, 8) in fp16.
__global__ void k_fill(const void* idx, const float* __restrict__ edge, int E) {
    int e = blockIdx.x * blockDim.x + threadIdx.x;
    if (e >= E) return;
    uint pr = g_rank[e];
    int o = (int)(pr >> 12);
    int in = idx_in32(idx, e);
    int p = g_offsets[o] + (int)(pr & 0xFFFu);
    g_src[p] = in;
    uint pk[4];
#pragma unroll
    for (int t = 0; t < 4; t++) {
        float w0 = edge[(size_t)(2 * t) * E + e];
        float w1 = edge[(size_t)(2 * t + 1) * E + e];
        pk[t] = (uint)__half_as_ushort(__float2half_rn(w0))
              | ((uint)__half_as_ushort(__float2half_rn(w1)) << 16);
    }
    *reinterpret_cast<uint4*>(g_edgeW + (size_t)p * 8) =
        make_uint4(pk[0], pk[1], pk[2], pk[3]);
}

// ---------------- edge accumulation: M[o, t*64+c] --------------------------------
// One warp per output; each lane owns channels (2*lane, 2*lane+1).  (R6 proven loop)
__global__ void k_accum(const float* __restrict__ node, int nOut) {
    int warp = (blockIdx.x * blockDim.x + threadIdx.x) >> 5;
    int lane = threadIdx.x & 31;
    if (warp >= nOut) return;

    int beg = g_offsets[warp];
    int end = g_offsets[warp + 1];

    float sx[T_DIM], sy[T_DIM];
#pragma unroll
    for (int t = 0; t < T_DIM; t++) { sx[t] = 0.f; sy[t] = 0.f; }

#pragma unroll 2
    for (int i = beg; i < end; i++) {
        int in = g_src[i];
        uint4 ew = *reinterpret_cast<const uint4*>(g_edgeW + (size_t)i * 8);
        float2 w0 = __half22float2(*reinterpret_cast<const __half2*>(&ew.x));
        float2 w1 = __half22float2(*reinterpret_cast<const __half2*>(&ew.y));
        float2 w2 = __half22float2(*reinterpret_cast<const __half2*>(&ew.z));
        float2 w3 = __half22float2(*reinterpret_cast<const __half2*>(&ew.w));
        float2 nv = *reinterpret_cast<const float2*>(&node[(size_t)in * C_DIM + lane * 2]);
        sx[0] += w0.x * nv.x; sy[0] += w0.x * nv.y;
        sx[1] += w0.y * nv.x; sy[1] += w0.y * nv.y;
        sx[2] += w1.x * nv.x; sy[2] += w1.x * nv.y;
        sx[3] += w1.y * nv.x; sy[3] += w1.y * nv.y;
        sx[4] += w2.x * nv.x; sy[4] += w2.x * nv.y;
        sx[5] += w2.y * nv.x; sy[5] += w2.y * nv.y;
        sx[6] += w3.x * nv.x; sy[6] += w3.x * nv.y;
        sx[7] += w3.y * nv.x; sy[7] += w3.y * nv.y;
    }

    int pc = permk(lane * 2);  // even; pair (pc, pc+1) is this lane's channel pair
    size_t base = (size_t)warp * TC_DIM + pc;
#pragma unroll
    for (int t = 0; t < T_DIM; t++) {
        uint pk = (uint)__half_as_ushort(__float2half_rn(sx[t]))
                | ((uint)__half_as_ushort(__float2half_rn(sy[t])) << 16);
        *reinterpret_cast<uint*>(&g_Mf[base + (size_t)t * 64]) = pk;
    }
}

// ---------------- GEMM via warp-level mma.sync (single fp16 product) -------------
__device__ __forceinline__ void mma16816(float* d, uint a0, uint a1, uint a2, uint a3,
                                         uint b0, uint b1) {
    asm volatile(
        "mma.sync.aligned.m16n8k16.row.col.f32.f16.f16.f32 "
        "{%0,%1,%2,%3}, {%4,%5,%6,%7}, {%8,%9}, {%0,%1,%2,%3};"
        : "+f"(d[0]), "+f"(d[1]), "+f"(d[2]), "+f"(d[3])
        : "r"(a0), "r"(a1), "r"(a2), "r"(a3), "r"(b0), "r"(b1));
}

__global__ __launch_bounds__(128) void k_gemm(const float* __restrict__ bias,
                                              float* __restrict__ out, int nOut) {
    int tid = threadIdx.x, w = tid >> 5, lane = tid & 31;
    int g = lane >> 2, t = lane & 3;
    int rowbase = blockIdx.x * 128 + w * 32;

    size_t abase = (size_t)(rowbase + g) * TC_DIM + t * 4;
    size_t bbase = (size_t)g * TC_DIM + t * 4;

    float d[2][8][4];
#pragma unroll
    for (int mt = 0; mt < 2; mt++)
#pragma unroll
        for (int nt = 0; nt < 8; nt++)
#pragma unroll
            for (int r = 0; r < 4; r++) d[mt][nt][r] = 0.f;

#pragma unroll 2
    for (int k0 = 0; k0 < TC_DIM; k0 += 16) {
        // A: 4 row-groups (g, g+8, g+16, g+24); each LDG.64 = 4 fp16 fragment elems.
        ull A0 = *reinterpret_cast<const ull*>(g_Mf + abase + k0);
        ull A1 = *reinterpret_cast<const ull*>(g_Mf + abase + 8 * TC_DIM + k0);
        ull A2 = *reinterpret_cast<const ull*>(g_Mf + abase + 16 * TC_DIM + k0);
        ull A3 = *reinterpret_cast<const ull*>(g_Mf + abase + 24 * TC_DIM + k0);
#pragma unroll
        for (int nt = 0; nt < 8; nt++) {
            ull Bv = *reinterpret_cast<const ull*>(g_Kf + bbase + (size_t)nt * 8 * TC_DIM + k0);
            uint b0 = (uint)Bv, b1 = (uint)(Bv >> 32);
            mma16816(d[0][nt], (uint)A0, (uint)A1, (uint)(A0 >> 32), (uint)(A1 >> 32), b0, b1);
            mma16816(d[1][nt], (uint)A2, (uint)A3, (uint)(A2 >> 32), (uint)(A3 >> 32), b0, b1);
        }
    }

    // Epilogue: d0=(g,2t) d1=(g,2t+1) d2=(g+8,2t) d3=(g+8,2t+1) per 16x8 tile.
#pragma unroll
    for (int mt = 0; mt < 2; mt++) {
#pragma unroll
        for (int nt = 0; nt < 8; nt++) {
            int col = nt * 8 + t * 2;
            float2 bv = *reinterpret_cast<const float2*>(bias + col);
            int r0 = rowbase + mt * 16 + g;
            if (r0 < nOut) {
                *reinterpret_cast<float2*>(&out[(size_t)r0 * F_DIM + col]) =
                    make_float2(d[mt][nt][0] + bv.x, d[mt][nt][1] + bv.y);
            }
            int r1 = r0 + 8;
            if (r1 < nOut) {
                *reinterpret_cast<float2*>(&out[(size_t)r1 * F_DIM + col]) =
                    make_float2(d[mt][nt][2] + bv.x, d[mt][nt][3] + bv.y);
            }
        }
    }
}

// ---------------- launch ---------------------------------------------------------
extern "C" void kernel_launch(void* const* d_in, const int* in_sizes, int n_in,
                              void* d_out, int out_size) {
    const float* node = (const float*)d_in[0];
    const float* edge = (const float*)d_in[1];
    const void*  idx  = d_in[2];
    const float* kern = (const float*)d_in[3];
    const float* bias = (const float*)d_in[4];
    float* out = (float*)d_out;

    int E    = in_sizes[1] / T_DIM;   // edge_features is (T, E)
    int nOut = out_size / F_DIM;      // output is (N_OUT, F)
    int nb   = (nOut + 1023) / 1024;  // <= 64

    k_init<<<(nOut + 255) / 256, 256>>>(nOut, idx, kern);
    k_hist<<<(E + 255) / 256, 256>>>(idx, E);
    k_scan<<<nb, 1024>>>(nOut, E);
    k_fill<<<(E + 255) / 256, 256>>>(idx, edge, E);
    k_accum<<<(nOut * 32 + 255) / 256, 256>>>(node, nOut);
    k_gemm<<<(nOut + 127) / 128, 128>>>(bias, out, nOut);
}